// round 17
// baseline (speedup 1.0000x reference)
#include <cuda_runtime.h>
#include <cuda_fp16.h>
#include <cstdint>

// ---------------------------------------------------------------------------
// SKConv2d via mma.sync (fp16 in / fp32 acc):
//   out = im2col(x) @ W_eff + 2*bias
// Kernel 1 (merged prologue):
//   blocks [0,144)      : build W transposed [o][k] fp16 — NO smem, direct
//                         vectorized loads (all operands L1-resident)
//   blocks [144,3280)   : convert+transpose x -> g_Xh[b][pixel][c] fp16
//                         (32px x 128ch tiles, 128B-line stores)
// Kernel 2: implicit GEMM, BM=64, BN=256, BK=64, 256 threads,
//           8 warps (2Mx4N), warp tile 32x64 via m16n8k16.
//           2-stage cp.async pipeline, 2 CTAs/SM, B-fragment ks-pipelining.
// ---------------------------------------------------------------------------

#define HH    56
#define WWd   56
#define Cc    128
#define OO    256
#define KK    1152
#define PLANE 3136
#define NN    100352
#define Tt    6
#define Rr    8
#define RR2   72

#define BM    64
#define BN    256
#define BK    64
#define NCHUNK 18          // 1152/64 ; tap = kt>>1
#define NSTAGE 2

// per stage: A 8KB (64 rows x 128B), B 32KB (256 rows x 128B)
#define STAGE_BYTES 40960
#define A_ST(s)  ((s) * STAGE_BYTES)
#define B_ST(s)  ((s) * STAGE_BYTES + 8192)
#define SMEM_BYTES (NSTAGE * STAGE_BYTES)      // 81920 -> 2 CTAs/SM

#define PRO_PRE_BLOCKS 144            // 36 x 4 W-precompute tiles
#define PRO_CVT_BLOCKS 3136           // 98 x 32 transpose tiles (32px x 128ch)

// W transposed fp16: g_Wh[o*KK + tap*128 + c]
__device__ __align__(16) __half g_Wh[OO * KK];
// x transposed fp16: g_Xh[(b*PLANE + p)*128 + c]
__device__ __align__(16) __half g_Xh[NN * Cc];

// ---------------------------------------------------------------------------
__device__ __forceinline__ uint32_t smem_u32(const void* p) {
    uint32_t a;
    asm("{ .reg .u64 t; cvta.to.shared.u64 t, %1; cvt.u32.u64 %0, t; }" : "=r"(a) : "l"(p));
    return a;
}
__device__ __forceinline__ uint32_t swz(uint32_t off) {   // 128B-row SW128 swizzle
    return off ^ ((off >> 3) & 0x70);
}
// pack two fp32 -> half2 bits; f0 -> low half (lower address)
__device__ __forceinline__ uint32_t pack_h2(float f0, float f1) {
    uint32_t r;
    asm("cvt.rn.f16x2.f32 %0, %1, %2;" : "=r"(r) : "f"(f1), "f"(f0));
    return r;
}
#define LDSM_X4(r0, r1, r2, r3, addr) \
    asm volatile("ldmatrix.sync.aligned.m8n8.x4.shared.b16 {%0,%1,%2,%3}, [%4];" \
        : "=r"(r0), "=r"(r1), "=r"(r2), "=r"(r3) : "r"(addr))
#define MMA16816(d, a0, a1, a2, a3, b0, b1)                                   \
    asm volatile("mma.sync.aligned.m16n8k16.row.col.f32.f16.f16.f32 "         \
        "{%0,%1,%2,%3}, {%4,%5,%6,%7}, {%8,%9}, {%0,%1,%2,%3};"               \
        : "+f"((d)[0]), "+f"((d)[1]), "+f"((d)[2]), "+f"((d)[3])              \
        : "r"(a0), "r"(a1), "r"(a2), "r"(a3), "r"(b0), "r"(b1))
#define CP_ASYNC16(dst, src) \
    asm volatile("cp.async.cg.shared.global [%0], [%1], 16;" :: "r"(dst), "l"(src) : "memory")
#define CP_ASYNC16Z(dst, src, sz) \
    asm volatile("cp.async.cg.shared.global [%0], [%1], 16, %2;" :: "r"(dst), "l"(src), "r"(sz) : "memory")
#define CP_COMMIT() asm volatile("cp.async.commit_group;" ::: "memory")
#define CP_WAIT1()  asm volatile("cp.async.wait_group 1;" ::: "memory")
#define CP_WAIT0()  asm volatile("cp.async.wait_group 0;" ::: "memory")

// ---------------------------------------------------------------------------
// Kernel 1: merged prologue. Grid 3280, block 256, 8.3KB smem.
// ---------------------------------------------------------------------------
__global__ void prologue(const float* __restrict__ x,
                         const float* __restrict__ S1s,
                         const float* __restrict__ U1s,
                         const float* __restrict__ U2s,
                         const float* __restrict__ S2s) {
    __shared__ uint32_t h2t[32][65];      // used by cvt blocks only
    const int tid = threadIdx.x;

    if (blockIdx.x < PRO_PRE_BLOCKS) {
        // ---------------- W_eff precompute: smem-free, vectorized ------------
        const int pid = blockIdx.x;
        const int d0 = (pid % 36) * 32;
        const int o0 = (pid / 36) * 64;
        const int dd = tid & 31;
        const int og = (tid >> 5) * 8;

        float acc[8];
#pragma unroll
        for (int j = 0; j < 8; j++) acc[j] = 0.f;

        const int d = d0 + dd;
        for (int t = 0; t < Tt; t++) {
            // term1: S1 row (8 consecutive floats) x U1 rows (8 consecutive)
            const float4* s1v = reinterpret_cast<const float4*>(
                                    S1s + (size_t)(t * KK + d) * Rr);
            const float4 s1a = __ldg(s1v);
            const float4 s1b = __ldg(s1v + 1);
            const float sa[8] = { s1a.x, s1a.y, s1a.z, s1a.w,
                                  s1b.x, s1b.y, s1b.z, s1b.w };
#pragma unroll
            for (int r = 0; r < Rr; r++) {
                const float4* u1v = reinterpret_cast<const float4*>(
                                        U1s + (size_t)(t * Rr + r) * OO + o0 + og);
                const float4 u0 = __ldg(u1v);
                const float4 u1 = __ldg(u1v + 1);
                const float a = sa[r];
                acc[0] += a * u0.x; acc[1] += a * u0.y;
                acc[2] += a * u0.z; acc[3] += a * u0.w;
                acc[4] += a * u1.x; acc[5] += a * u1.y;
                acc[6] += a * u1.z; acc[7] += a * u1.w;
            }
            // term2: U2 column scalar x S2 rows (8 consecutive)
#pragma unroll 4
            for (int r2 = 0; r2 < RR2; r2++) {
                const float a = __ldg(U2s + (size_t)(t * RR2 + r2) * KK + d);
                const float4* s2v = reinterpret_cast<const float4*>(
                                        S2s + (size_t)(t * RR2 + r2) * OO + o0 + og);
                const float4 v0 = __ldg(s2v);
                const float4 v1 = __ldg(s2v + 1);
                acc[0] += a * v0.x; acc[1] += a * v0.y;
                acc[2] += a * v0.z; acc[3] += a * v0.w;
                acc[4] += a * v1.x; acc[5] += a * v1.y;
                acc[6] += a * v1.z; acc[7] += a * v1.w;
            }
        }

        const int c   = d / 9;
        const int tap = d - 9 * c;
        const int krow = tap * 128 + c;
#pragma unroll
        for (int j = 0; j < 8; j++)
            g_Wh[(o0 + og + j) * KK + krow] = __float2half_rn(acc[j] * (1.0f / 6.0f));
    } else {
        // ---------------- x convert + transpose (128B-line stores) -----------
        const int bid = blockIdx.x - PRO_PRE_BLOCKS;   // 0..3135
        const int b   = bid / 98;                      // 0..31
        const int p0  = (bid - b * 98) * 32;
        const int px  = tid & 31;
        const int ty  = tid >> 5;             // 0..7

        const float* xb = x + (size_t)b * Cc * PLANE + p0 + px;
#pragma unroll
        for (int i = 0; i < 8; i++) {
            const int ch2 = ty + 8 * i;       // half2 index 0..63
            const float f0 = xb[(size_t)(2 * ch2)     * PLANE];
            const float f1 = xb[(size_t)(2 * ch2 + 1) * PLANE];
            h2t[px][ch2] = pack_h2(f0, f1);
        }
        __syncthreads();

        uint32_t* dst = reinterpret_cast<uint32_t*>(g_Xh + (size_t)(b * PLANE + p0) * Cc);
        const int lane = tid & 31, w = tid >> 5;
#pragma unroll
        for (int i = 0; i < 4; i++) {
            const int p = w * 4 + i;
            dst[p * 64 + lane]      = h2t[p][lane];        // 128B line
            dst[p * 64 + 32 + lane] = h2t[p][lane + 32];   // 128B line
        }
    }
}

// ---------------------------------------------------------------------------
// Kernel 2: mma.sync implicit GEMM conv. Grid 1568, block 256, 80KB dyn smem.
// ---------------------------------------------------------------------------
__global__ __launch_bounds__(256, 2)
void conv_mma(const float* __restrict__ bias,
              float* __restrict__ out) {
    extern __shared__ __align__(16) char smem[];
    const uint32_t sb = smem_u32(smem);

    const int tid  = threadIdx.x;
    const int lane = tid & 31;
    const int wid  = tid >> 5;
    const int wm   = wid & 1;      // 2 warps in M (32 rows each)
    const int wn   = wid >> 1;     // 4 warps in N (64 cols each)
    const int bm0  = blockIdx.x * BM;

    // ---- A-copy geometry: row ar = tid>>2 (0..63), segs 2*(tid&3)+{0,1} ----
    const int ar   = tid >> 2;
    const int asg0 = (tid & 3) * 2;
    const int am   = bm0 + ar;
    const int ab   = am / PLANE;
    const int arem = am - ab * PLANE;
    const int aoh  = arem / WWd;
    const int aow  = arem - aoh * WWd;

    const char* xbase = reinterpret_cast<const char*>(g_Xh);
    int      xoff[9];        // byte offset of im2col row per tap (fits 32-bit)
    uint32_t xmask = 0;      // per-tap validity bit
#pragma unroll
    for (int tap = 0; tap < 9; tap++) {
        const int kh = tap / 3, kw = tap - 3 * kh;
        const int ih = aoh + kh - 1, iw = aow + kw - 1;
        const bool ok = ((unsigned)ih < HH) && ((unsigned)iw < WWd);
        const int off = ok ? (ih * WWd + iw) : 0;
        xoff[tap] = (ab * PLANE + off) * (Cc * 2);
        if (ok) xmask |= (1u << tap);
    }
    const char* wb = reinterpret_cast<const char*>(g_Wh);

    auto issueChunk = [&](int kt, int s) {
        const int tap = kt >> 1;
        const int c0b = (kt & 1) * 128;          // chunk channel-offset in bytes
        const uint32_t sz = ((xmask >> tap) & 1u) * 16u;
        const char* src = xbase + xoff[tap] + c0b;
        // A: 512 x 16B (this thread: 2, same row)
#pragma unroll
        for (int i = 0; i < 2; i++) {
            const int seg = asg0 + i;
            CP_ASYNC16Z(sb + A_ST(s) + swz(ar * 128 + seg * 16),
                        src + seg * 16, sz);
        }
        // B: 2048 x 16B (this thread: 8)
        const int k0 = kt * BK;
#pragma unroll
        for (int i = 0; i < 8; i++) {
            int f = tid + i * 256;
            int n = f >> 3, seg = f & 7;
            CP_ASYNC16(sb + B_ST(s) + swz(n * 128 + seg * 16),
                       wb + (size_t)(n * KK + k0 + seg * 8) * 2);
        }
        CP_COMMIT();
    };

    float acc[2][8][4];
#pragma unroll
    for (int i = 0; i < 2; i++)
#pragma unroll
        for (int j = 0; j < 8; j++)
#pragma unroll
            for (int q = 0; q < 4; q++) acc[i][j][q] = 0.f;

    issueChunk(0, 0); issueChunk(1, 1);

#pragma unroll 1
    for (int kt = 0; kt < NCHUNK; kt++) {
        CP_WAIT1();                // group kt complete (<=1 group pending)
        __syncthreads();           // chunk kt visible to all threads

        const int s = kt & 1;
        const uint32_t aB = sb + A_ST(s);
        const uint32_t bB = sb + B_ST(s);

        // B fragments double-buffered across ks: load ks+1 under ks's mmas.
        uint32_t bf[2][8][2];
#pragma unroll
        for (int jj = 0; jj < 4; jj++) {        // preload ks=0
            const int nr = wn * 64 + jj * 16 + ((lane >> 4) & 1) * 8 + (lane & 7);
            const int kc = ((lane >> 3) & 1) * 8;
            LDSM_X4(bf[0][2 * jj][0], bf[0][2 * jj][1],
                    bf[0][2 * jj + 1][0], bf[0][2 * jj + 1][1],
                    bB + swz(nr * 128 + kc * 2));
        }
#pragma unroll
        for (int ks = 0; ks < 4; ks++) {
            const int k0 = ks * 16;
            uint32_t af[2][4];
#pragma unroll
            for (int i = 0; i < 2; i++) {
                const int mr = wm * 32 + i * 16 + (lane & 15);
                const int kc = k0 + (lane >> 4) * 8;
                LDSM_X4(af[i][0], af[i][1], af[i][2], af[i][3],
                        aB + swz(mr * 128 + kc * 2));
            }
            if (ks < 3) {
                const int k0n = k0 + 16;
#pragma unroll
                for (int jj = 0; jj < 4; jj++) {
                    const int nr = wn * 64 + jj * 16 + ((lane >> 4) & 1) * 8 + (lane & 7);
                    const int kc = k0n + ((lane >> 3) & 1) * 8;
                    LDSM_X4(bf[(ks + 1) & 1][2 * jj][0], bf[(ks + 1) & 1][2 * jj][1],
                            bf[(ks + 1) & 1][2 * jj + 1][0], bf[(ks + 1) & 1][2 * jj + 1][1],
                            bB + swz(nr * 128 + kc * 2));
                }
            }
#pragma unroll
            for (int i = 0; i < 2; i++)
#pragma unroll
                for (int j = 0; j < 8; j++)
                    MMA16816(acc[i][j], af[i][0], af[i][1], af[i][2], af[i][3],
                             bf[ks & 1][j][0], bf[ks & 1][j][1]);
        }

        __syncthreads();           // all reads of stage s done before refill
        if (kt + 2 < NCHUNK) issueChunk(kt + 2, s);
        else                 CP_COMMIT();    // keep group count aligned
    }
    CP_WAIT0();

    // ---- epilogue: thread lane holds rows (l>>2, l>>2+8), cols 2*(l&3)+{0,1} ----
#pragma unroll
    for (int i = 0; i < 2; i++) {
        const int mg0 = bm0 + wm * 32 + i * 16 + (lane >> 2);
        const int b0e = mg0 / PLANE;
        const int p0e = mg0 - b0e * PLANE;
        const int mg1 = mg0 + 8;
        const int b1e = mg1 / PLANE;
        const int p1e = mg1 - b1e * PLANE;
        float* o0 = out + (size_t)b0e * (OO * PLANE) + p0e;
        float* o1 = out + (size_t)b1e * (OO * PLANE) + p1e;
#pragma unroll
        for (int j = 0; j < 8; j++) {
            const int o = wn * 64 + j * 8 + (lane & 3) * 2;
            const float bv0 = 2.0f * __ldg(bias + o);
            const float bv1 = 2.0f * __ldg(bias + o + 1);
            o0[(size_t)o * PLANE]       = acc[i][j][0] + bv0;
            o0[(size_t)(o + 1) * PLANE] = acc[i][j][1] + bv1;
            o1[(size_t)o * PLANE]       = acc[i][j][2] + bv0;
            o1[(size_t)(o + 1) * PLANE] = acc[i][j][3] + bv1;
        }
    }
}

// ---------------------------------------------------------------------------
extern "C" void kernel_launch(void* const* d_in, const int* in_sizes, int n_in,
                              void* d_out, int out_size) {
    const float* x    = (const float*)d_in[0];
    const float* S1s  = (const float*)d_in[1];
    const float* U1s  = (const float*)d_in[2];
    const float* U2s  = (const float*)d_in[3];
    const float* S2s  = (const float*)d_in[4];
    const float* bias = (const float*)d_in[5];
    float* out = (float*)d_out;

    cudaFuncSetAttribute(conv_mma, cudaFuncAttributeMaxDynamicSharedMemorySize,
                         SMEM_BYTES);

    prologue<<<PRO_PRE_BLOCKS + PRO_CVT_BLOCKS, 256>>>(x, S1s, U1s, U2s, S2s);
    conv_mma<<<1568, 256, SMEM_BYTES>>>(bias, out);
}